// round 5
// baseline (speedup 1.0000x reference)
#include <cuda_runtime.h>

// Problem constants (fixed by the dataset)
#define BATCH 32
#define HW    196      // 14*14 spatial positions
#define C     512      // input channels
#define D     8192     // sketch / output dimension
#define KT    14       // K-chunk for shared tiles (196 = 14*14)
#define BCH   4        // batches per CTA (packed into v4 atomics)

typedef unsigned long long ull;

// Transposed global accumulator [D][BATCH]: the 32 batch values of one
// bucket are contiguous, enabling red.global.add.v4.f32 (4 batches/atomic).
__device__ float g_out_t[D * BATCH];   // 1 MB static scratch

// Packed fp32x2 FMA (Blackwell): acc = a2 * b2 + acc  (2 independent FMAs)
#define FMA2(acc, a2, b2) \
    asm("fma.rn.f32x2 %0, %1, %2, %0;" : "+l"(acc) : "l"(a2), "l"(b2))
#define PACK2(o, lo, hi) \
    asm("mov.b64 %0, {%1, %2};" : "=l"(o) : "f"(lo), "f"(hi))
#define UNPACK2(lo, hi, in) \
    asm("mov.b64 {%0, %1}, %2;" : "=f"(lo), "=f"(hi) : "l"(in))

// grid (8, 8, 8): blockIdx.x = c1 tile (64), blockIdx.y = c2 tile (64),
// blockIdx.z = batch chunk (4 batches). 256 threads, 4x4 products x 4
// batches per thread; the batch axis rides the fp32x2 lanes, so FFMA2
// count is identical to the per-batch kernel. Scatter: one v4 global RED
// per (c1,c2) product covering all 4 batches -> 2.1M atomics chip-wide.
__global__ __launch_bounds__(256, 2)
void cbp_gemm_scatter(const float* __restrict__ x1, const float* __restrict__ x2,
                      const float* __restrict__ s1, const float* __restrict__ s2,
                      const int*   __restrict__ h1, const int*   __restrict__ h2)
{
    // batch-interleaved tiles: [kk][channel][batch], 14 KB each
    __shared__ float X1s[KT][64][BCH];
    __shared__ float X2s[KT][64][BCH];

    const int tid = threadIdx.x;
    const int tx  = tid & 15;            // c2 quad
    const int ty  = tid >> 4;            // c1 quad
    const int c1_base = blockIdx.x * 64;
    const int c2_base = blockIdx.y * 64;
    const int bbase   = blockIdx.z * BCH;

    // loader mapping: c = tid & 63 (constant per thread), kk = (tid>>6) + 4n
    const int lc  = tid & 63;
    const int kks = tid >> 6;
    const float s1l = __ldg(&s1[c1_base + lc]);
    const float s2l = __ldg(&s2[c2_base + lc]);

    const float* p1base = x1 + (size_t)bbase * HW * C + c1_base + lc;
    const float* p2base = x2 + (size_t)bbase * HW * C + c2_base + lc;
    const size_t bstr = (size_t)HW * C;  // batch stride in elements

    // acc[i][j][p]: fp32x2 over batch pairs (p=0: b0,b1; p=1: b2,b3)
    ull acc[4][4][2];
    #pragma unroll
    for (int i = 0; i < 4; i++)
        #pragma unroll
        for (int j = 0; j < 4; j++) { acc[i][j][0] = 0ULL; acc[i][j][1] = 0ULL; }

    for (int k0 = 0; k0 < HW; k0 += KT) {
        __syncthreads();   // protect tiles from previous iteration's readers
        #pragma unroll
        for (int n = 0; n < 4; ++n) {          // 14*64 slots / 256 threads
            int kk = kks + 4 * n;
            if (kk < KT) {
                const float* p1 = p1base + (size_t)(k0 + kk) * C;
                const float* p2 = p2base + (size_t)(k0 + kk) * C;
                float4 v1, v2;                  // 4 batches for one channel
                v1.x = p1[0]        * s1l;  v1.y = p1[bstr]     * s1l;
                v1.z = p1[2 * bstr] * s1l;  v1.w = p1[3 * bstr] * s1l;
                v2.x = p2[0]        * s2l;  v2.y = p2[bstr]     * s2l;
                v2.z = p2[2 * bstr] * s2l;  v2.w = p2[3 * bstr] * s2l;
                *(float4*)&X1s[kk][lc][0] = v1;   // STS.128, conflict-free
                *(float4*)&X2s[kk][lc][0] = v2;
            }
        }
        __syncthreads();

        #pragma unroll
        for (int kk = 0; kk < KT; ++kk) {
            ull a2[4][2], b2[4][2];
            #pragma unroll
            for (int i = 0; i < 4; i++) {       // broadcast across tx
                float4 av = *(const float4*)&X1s[kk][ty * 4 + i][0];
                PACK2(a2[i][0], av.x, av.y);
                PACK2(a2[i][1], av.z, av.w);
            }
            #pragma unroll
            for (int j = 0; j < 4; j++) {
                float4 bv = *(const float4*)&X2s[kk][tx * 4 + j][0];
                PACK2(b2[j][0], bv.x, bv.y);
                PACK2(b2[j][1], bv.z, bv.w);
            }
            #pragma unroll
            for (int i = 0; i < 4; i++)
                #pragma unroll
                for (int j = 0; j < 4; j++) {
                    FMA2(acc[i][j][0], a2[i][0], b2[j][0]);
                    FMA2(acc[i][j][1], a2[i][1], b2[j][1]);
                }
        }
    }

    // ---- scatter: one v4 RED per (c1,c2) product, 4 batches at once ----
    int h1v[4], h2v[4];
    #pragma unroll
    for (int i = 0; i < 4; i++) h1v[i] = __ldg(&h1[c1_base + ty * 4 + i]);
    #pragma unroll
    for (int j = 0; j < 4; j++) h2v[j] = __ldg(&h2[c2_base + tx * 4 + j]);

    float* base = g_out_t + bbase;      // 16B-aligned (bbase multiple of 4)
    #pragma unroll
    for (int i = 0; i < 4; i++)
        #pragma unroll
        for (int j = 0; j < 4; j++) {
            int d = (h1v[i] + h2v[j]) & (D - 1);
            float v0, v1, v2, v3;
            UNPACK2(v0, v1, acc[i][j][0]);
            UNPACK2(v2, v3, acc[i][j][1]);
            asm volatile("red.global.add.v4.f32 [%0], {%1, %2, %3, %4};"
                         :: "l"(base + (size_t)d * BATCH),
                            "f"(v0), "f"(v1), "f"(v2), "f"(v3) : "memory");
        }
}

__global__ void zero_scratch_kernel()
{
    int i = blockIdx.x * blockDim.x + threadIdx.x;   // 65536 float4s
    ((float4*)g_out_t)[i] = make_float4(0.f, 0.f, 0.f, 0.f);
}

// out[b][d] = g_out_t[d][b]; contiguous per-thread row read, coalesced writes
__global__ void transpose_out_kernel(float* __restrict__ out)
{
    int d = blockIdx.x * blockDim.x + threadIdx.x;   // 8192 threads
    float4 v[8];
    const float4* row = (const float4*)(g_out_t + (size_t)d * BATCH);
    #pragma unroll
    for (int q = 0; q < 8; q++) v[q] = row[q];
    const float* vf = (const float*)v;
    #pragma unroll
    for (int b = 0; b < BATCH; b++) out[(size_t)b * D + d] = vf[b];
}

extern "C" void kernel_launch(void* const* d_in, const int* in_sizes, int n_in,
                              void* d_out, int out_size)
{
    const float* x1 = (const float*)d_in[0];   // bottom1 [32,14,14,512]
    const float* x2 = (const float*)d_in[1];   // bottom2 [32,14,14,512]
    const float* s1 = (const float*)d_in[2];   // rand_s_1 [512]
    const float* s2 = (const float*)d_in[3];   // rand_s_2 [512]
    const int*   h1 = (const int*)d_in[4];     // rand_h_1 [512]
    const int*   h2 = (const int*)d_in[5];     // rand_h_2 [512]
    float* out = (float*)d_out;                // [32, 8192] float32

    zero_scratch_kernel<<<(D * BATCH / 4 + 255) / 256, 256>>>();

    dim3 grid(C / 64, C / 64, BATCH / BCH);    // (8, 8, 8) = 512 CTAs
    cbp_gemm_scatter<<<grid, 256>>>(x1, x2, s1, s2, h1, h2);

    transpose_out_kernel<<<D / 256, 256>>>(out);
}